// round 14
// baseline (speedup 1.0000x reference)
#include <cuda_runtime.h>
#include <cuda_bf16.h>
#include <cstdint>

#define N_NODES 100000
#define N_EDGES 1600000
#define IN_F    512
#define HID_F   128
#define N_CLS   64
#define HALF_N  50048            // split point, multiple of 128 and 8

// ---------------- device scratch (no allocations allowed) ----------------
__device__ __align__(16) float g_h1[(size_t)N_NODES * HID_F];
__device__ __align__(16) float g_h2[(size_t)N_NODES * HID_F];
__device__ __align__(16) float g_h3[(size_t)N_NODES * N_CLS];
__device__ int   g_deg[N_NODES + 1];
__device__ int   g_rowptr[N_NODES + 1];
__device__ int   g_fill[N_NODES];
__device__ int2  g_edge[N_EDGES];                 // {col, float_bits(val)}
__device__ __align__(16) __nv_bfloat16 g_w1t_hi[HID_F * IN_F];   // [128][512]
__device__ __align__(16) __nv_bfloat16 g_w1t_lo[HID_F * IN_F];
__device__ __align__(16) __nv_bfloat16 g_w2t_hi[N_CLS * HID_F];  // [64][128]
__device__ __align__(16) __nv_bfloat16 g_w2t_lo[N_CLS * HID_F];

// ---------------- small helpers ----------------
__device__ __forceinline__ uint32_t smem_u32(const void* p) {
    uint32_t a;
    asm("{ .reg .u64 t; cvta.to.shared.u64 t, %1; cvt.u32.u64 %0, t; }" : "=r"(a) : "l"(p));
    return a;
}
__device__ __forceinline__ void cp16(uint32_t dst, const void* src) {
    asm volatile("cp.async.ca.shared.global [%0], [%1], 16;" :: "r"(dst), "l"(src));
}
#define CP_COMMIT() asm volatile("cp.async.commit_group;" ::: "memory")
#define CP_WAIT(n)  asm volatile("cp.async.wait_group %0;" :: "n"(n) : "memory")

__device__ __forceinline__ void mma_bf16(float* c, const uint32_t* a, const uint32_t* b) {
    asm volatile(
        "mma.sync.aligned.m16n8k16.row.col.f32.bf16.bf16.f32 "
        "{%0,%1,%2,%3}, {%4,%5,%6,%7}, {%8,%9}, {%0,%1,%2,%3};"
        : "+f"(c[0]), "+f"(c[1]), "+f"(c[2]), "+f"(c[3])
        : "r"(a[0]), "r"(a[1]), "r"(a[2]), "r"(a[3]), "r"(b[0]), "r"(b[1]));
}
__device__ __forceinline__ uint32_t pack_bf16x2(__nv_bfloat16 a, __nv_bfloat16 b) {
    __nv_bfloat162 p; p.x = a; p.y = b;
    return *reinterpret_cast<uint32_t*>(&p);
}
// FAST split: hi = truncate-to-bf16 (exact top 16 bits), lo = rn(v - hi).
__device__ __forceinline__ uint32_t split2(float2 v, uint32_t& lo) {
    uint32_t u0 = __float_as_uint(v.x);
    uint32_t u1 = __float_as_uint(v.y);
    float l0 = v.x - __uint_as_float(u0 & 0xFFFF0000u);
    float l1 = v.y - __uint_as_float(u1 & 0xFFFF0000u);
    uint32_t hi, lou;
    asm("prmt.b32 %0, %1, %2, 0x7632;" : "=r"(hi) : "r"(u0), "r"(u1));
    asm("cvt.rn.bf16x2.f32 %0, %1, %2;" : "=r"(lou) : "f"(l1), "f"(l0));
    lo = lou;
    return hi;
}

// ---------------- CSR build ----------------
__global__ void zero_deg_kernel() {
    int i = blockIdx.x * blockDim.x + threadIdx.x;
    if (i <= N_NODES) g_deg[i] = 0;
}
__global__ void count_kernel(const int* __restrict__ row) {
    int e = blockIdx.x * blockDim.x + threadIdx.x;
    if (e < N_EDGES) atomicAdd(&g_deg[row[e]], 1);
}
__global__ __launch_bounds__(1024) void scan_kernel() {
    __shared__ int wsum[32];
    int t = threadIdx.x;
    const int CH = (N_NODES + 1023) / 1024;  // 98
    int base = t * CH;
    int s = 0;
#pragma unroll 4
    for (int j = 0; j < CH; j++) {
        int i = base + j;
        if (i < N_NODES) s += g_deg[i];
    }
    int lane = t & 31, wid = t >> 5;
    int v = s;
#pragma unroll
    for (int d = 1; d < 32; d <<= 1) {
        int n = __shfl_up_sync(0xFFFFFFFF, v, d);
        if (lane >= d) v += n;
    }
    if (lane == 31) wsum[wid] = v;
    __syncthreads();
    if (wid == 0) {
        int w = wsum[lane];
#pragma unroll
        for (int d = 1; d < 32; d <<= 1) {
            int n = __shfl_up_sync(0xFFFFFFFF, w, d);
            if (lane >= d) w += n;
        }
        wsum[lane] = w;
    }
    __syncthreads();
    int run = v - s + (wid ? wsum[wid - 1] : 0);
    for (int j = 0; j < CH; j++) {
        int i = base + j;
        if (i < N_NODES) {
            int d = g_deg[i];
            g_rowptr[i] = run;
            g_fill[i]   = run;
            run += d;
        }
    }
    if (t == 1023) g_rowptr[N_NODES] = N_EDGES;
}
__global__ void scatter_kernel(const int* __restrict__ row, const int* __restrict__ col,
                               const float* __restrict__ val) {
    int e = blockIdx.x * blockDim.x + threadIdx.x;
    if (e < N_EDGES) {
        int r = row[e];
        int p = atomicAdd(&g_fill[r], 1);
        g_edge[p] = make_int2(col[e], __float_as_int(val[e]));
    }
}

// ---------------- weight prep: transpose + bf16 hi/lo split ----------------
__global__ void prep_w1t_kernel(const float* __restrict__ w1) {
    int idx = blockIdx.x * blockDim.x + threadIdx.x;
    if (idx < IN_F * HID_F) {
        int k = idx >> 7, n = idx & 127;
        float v = w1[idx];
        __nv_bfloat16 h = __float2bfloat16(v);
        float r = v - __bfloat162float(h);
        g_w1t_hi[n * IN_F + k] = h;
        g_w1t_lo[n * IN_F + k] = __float2bfloat16(r);
    }
}
__global__ void prep_w2t_kernel(const float* __restrict__ w2) {
    int idx = blockIdx.x * blockDim.x + threadIdx.x;
    if (idx < HID_F * N_CLS) {
        int k = idx >> 6, n = idx & 63;
        float v = w2[idx];
        __nv_bfloat16 h = __float2bfloat16(v);
        float r = v - __bfloat162float(h);
        g_w2t_hi[n * HID_F + k] = h;
        g_w2t_lo[n * HID_F + k] = __float2bfloat16(r);
    }
}

// ---------------- cp.async pipelined bf16-split GEMM (R7-proven) ------------
#define BK  64
#define LDK 72
#define LDA 68

template <int BN, int K_TOTAL>
__global__ __launch_bounds__(256) void gemm_pipe_kernel(
    const float* __restrict__ X,
    const __nv_bfloat16* __restrict__ Wt_hi,
    const __nv_bfloat16* __restrict__ Wt_lo,
    const float* __restrict__ Bias,
    float* __restrict__ O,
    int row_base, int row_limit) {
    constexpr int NITER = K_TOTAL / BK;
    extern __shared__ char smraw[];
    float* Af = (float*)smraw;                                   // [2][128][LDA]
    __nv_bfloat16* Bh = (__nv_bfloat16*)(Af + 2 * 128 * LDA);    // [BN][LDK]
    __nv_bfloat16* Bl = Bh + BN * LDK;

    const int t = threadIdx.x;
    const int lane = t & 31;
    const int wid = t >> 5;
    const int warp_m = wid & 3;
    const int warp_n = wid >> 2;
    const int NT = BN / 16;
    const int n0 = warp_n * (BN / 2);
    const int row0 = row_base + blockIdx.x * 128;
    const int gq = lane >> 2;
    const int gc2 = (lane & 3) * 2;

    const uint32_t af_u = smem_u32(Af);
    const uint32_t bh_u = smem_u32(Bh);
    const uint32_t bl_u = smem_u32(Bl);

    auto issueA = [&](int s) {
        const int buf = s & 1;
        const int k0 = s * BK;
#pragma unroll
        for (int i = 0; i < 8; i++) {
            int idx = t + i * 256;
            int row = idx >> 4, c4 = (idx & 15) * 4;
            int gr = row0 + row;
            if (gr >= N_NODES) gr = N_NODES - 1;
            cp16(af_u + (uint32_t)(((buf * 128 + row) * LDA + c4) * 4),
                 X + (size_t)gr * K_TOTAL + k0 + c4);
        }
    };
    auto issueB = [&](int s) {
        const int k0 = s * BK;
        constexpr int BCH = BN * 8 / 256;
#pragma unroll
        for (int i = 0; i < BCH; i++) {
            int idx = t + i * 256;
            int row = idx >> 3, q = (idx & 7) * 8;
            cp16(bh_u + (uint32_t)((row * LDK + q) * 2),
                 Wt_hi + (size_t)row * K_TOTAL + k0 + q);
            cp16(bl_u + (uint32_t)((row * LDK + q) * 2),
                 Wt_lo + (size_t)row * K_TOTAL + k0 + q);
        }
    };

    float acc[2][BN / 16][4];
#pragma unroll
    for (int mt = 0; mt < 2; mt++)
#pragma unroll
        for (int nt = 0; nt < NT; nt++)
#pragma unroll
            for (int i = 0; i < 4; i++) acc[mt][nt][i] = 0.f;

    issueB(0); CP_COMMIT();
    issueA(0); CP_COMMIT();
    if (NITER > 1) { issueA(1); CP_COMMIT(); CP_WAIT(1); }
    else           { CP_WAIT(0); }
    __syncthreads();

    for (int c = 0; c < NITER; c++) {
        const int buf = c & 1;
#pragma unroll
        for (int ks = 0; ks < 4; ks++) {
            const int k = ks * 16;
            uint32_t ah[2][4], al[2][4];
#pragma unroll
            for (int mt = 0; mt < 2; mt++) {
                const int rb = buf * 128 + warp_m * 32 + mt * 16 + gq;
                const float* p0 = &Af[rb * LDA + k + gc2];
                float2 v0 = *(const float2*)(p0);
                float2 v1 = *(const float2*)(p0 + 8 * LDA);
                float2 v2 = *(const float2*)(p0 + 8);
                float2 v3 = *(const float2*)(p0 + 8 * LDA + 8);
                ah[mt][0] = split2(v0, al[mt][0]);
                ah[mt][1] = split2(v1, al[mt][1]);
                ah[mt][2] = split2(v2, al[mt][2]);
                ah[mt][3] = split2(v3, al[mt][3]);
            }
#pragma unroll
            for (int nt = 0; nt < NT; nt++) {
                const int nrow = n0 + nt * 8 + gq;
                const __nv_bfloat16* ph = &Bh[nrow * LDK + k + gc2];
                const __nv_bfloat16* pl = &Bl[nrow * LDK + k + gc2];
                uint32_t bh[2], bl[2];
                bh[0] = *(const uint32_t*)(ph);
                bh[1] = *(const uint32_t*)(ph + 8);
                bl[0] = *(const uint32_t*)(pl);
                bl[1] = *(const uint32_t*)(pl + 8);
#pragma unroll
                for (int mt = 0; mt < 2; mt++) {
                    mma_bf16(acc[mt][nt], ah[mt], bh);
                    mma_bf16(acc[mt][nt], ah[mt], bl);
                    mma_bf16(acc[mt][nt], al[mt], bh);
                }
            }
        }
        __syncthreads();
        if (c + 1 < NITER) {
            issueB(c + 1); CP_COMMIT();
            if (c + 2 < NITER) { issueA(c + 2); CP_COMMIT(); CP_WAIT(1); }
            else               { CP_WAIT(0); }
            __syncthreads();
        }
    }

#pragma unroll
    for (int nt = 0; nt < NT; nt++) {
        const int colb = n0 + nt * 8 + gc2;
        float2 bb = *(const float2*)&Bias[colb];
#pragma unroll
        for (int mt = 0; mt < 2; mt++) {
            int r0 = row0 + warp_m * 32 + mt * 16 + gq;
            if (r0 < row_limit) {
                float2 o0;
                o0.x = acc[mt][nt][0] + bb.x;
                o0.y = acc[mt][nt][1] + bb.y;
                *(float2*)&O[(size_t)r0 * BN + colb] = o0;
            }
            int r1 = r0 + 8;
            if (r1 < row_limit) {
                float2 o1;
                o1.x = acc[mt][nt][2] + bb.x;
                o1.y = acc[mt][nt][3] + bb.y;
                *(float2*)&O[(size_t)r1 * BN + colb] = o1;
            }
        }
    }
}

// ---------------- SpMM: warp-per-node, 8-edge unroll (MLP=8) ----------------
__global__ __launch_bounds__(256) void spmm1_warp_kernel(
    const float* __restrict__ h1, float* __restrict__ h2, int node_base) {
    int node = node_base + blockIdx.x * 8 + (threadIdx.x >> 5);
    int lane = threadIdx.x & 31;
    int s = g_rowptr[node], e = g_rowptr[node + 1];

    float4 a0 = make_float4(0.f, 0.f, 0.f, 0.f);
    float4 a1 = a0, a2 = a0, a3 = a0;
    const float4* H = (const float4*)h1;

    int j = s;
    for (; j + 7 < e; j += 8) {
        int2 e0 = g_edge[j],     e1 = g_edge[j + 1];
        int2 e2 = g_edge[j + 2], e3 = g_edge[j + 3];
        int2 e4 = g_edge[j + 4], e5 = g_edge[j + 5];
        int2 e6 = g_edge[j + 6], e7 = g_edge[j + 7];
        float4 x0 = H[(size_t)e0.x * 32 + lane];
        float4 x1 = H[(size_t)e1.x * 32 + lane];
        float4 x2 = H[(size_t)e2.x * 32 + lane];
        float4 x3 = H[(size_t)e3.x * 32 + lane];
        float4 x4 = H[(size_t)e4.x * 32 + lane];
        float4 x5 = H[(size_t)e5.x * 32 + lane];
        float4 x6 = H[(size_t)e6.x * 32 + lane];
        float4 x7 = H[(size_t)e7.x * 32 + lane];
        float v0 = __int_as_float(e0.y), v1 = __int_as_float(e1.y);
        float v2 = __int_as_float(e2.y), v3 = __int_as_float(e3.y);
        float v4 = __int_as_float(e4.y), v5 = __int_as_float(e5.y);
        float v6 = __int_as_float(e6.y), v7 = __int_as_float(e7.y);
        a0.x += v0 * x0.x; a0.y += v0 * x0.y; a0.z += v0 * x0.z; a0.w += v0 * x0.w;
        a1.x += v1 * x1.x; a1.y += v1 * x1.y; a1.z += v1 * x1.z; a1.w += v1 * x1.w;
        a2.x += v2 * x2.x; a2.y += v2 * x2.y; a2.z += v2 * x2.z; a2.w += v2 * x2.w;
        a3.x += v3 * x3.x; a3.y += v3 * x3.y; a3.z += v3 * x3.z; a3.w += v3 * x3.w;
        a0.x += v4 * x4.x; a0.y += v4 * x4.y; a0.z += v4 * x4.z; a0.w += v4 * x4.w;
        a1.x += v5 * x5.x; a1.y += v5 * x5.y; a1.z += v5 * x5.z; a1.w += v5 * x5.w;
        a2.x += v6 * x6.x; a2.y += v6 * x6.y; a2.z += v6 * x6.z; a2.w += v6 * x6.w;
        a3.x += v7 * x7.x; a3.y += v7 * x7.y; a3.z += v7 * x7.z; a3.w += v7 * x7.w;
    }
    for (; j + 3 < e; j += 4) {
        int2 e0 = g_edge[j],     e1 = g_edge[j + 1];
        int2 e2 = g_edge[j + 2], e3 = g_edge[j + 3];
        float v0 = __int_as_float(e0.y), v1 = __int_as_float(e1.y);
        float v2 = __int_as_float(e2.y), v3 = __int_as_float(e3.y);
        float4 x0 = H[(size_t)e0.x * 32 + lane];
        float4 x1 = H[(size_t)e1.x * 32 + lane];
        float4 x2 = H[(size_t)e2.x * 32 + lane];
        float4 x3 = H[(size_t)e3.x * 32 + lane];
        a0.x += v0 * x0.x; a0.y += v0 * x0.y; a0.z += v0 * x0.z; a0.w += v0 * x0.w;
        a1.x += v1 * x1.x; a1.y += v1 * x1.y; a1.z += v1 * x1.z; a1.w += v1 * x1.w;
        a2.x += v2 * x2.x; a2.y += v2 * x2.y; a2.z += v2 * x2.z; a2.w += v2 * x2.w;
        a3.x += v3 * x3.x; a3.y += v3 * x3.y; a3.z += v3 * x3.z; a3.w += v3 * x3.w;
    }
    for (; j < e; j++) {
        int2 ed = g_edge[j];
        float v = __int_as_float(ed.y);
        float4 x = H[(size_t)ed.x * 32 + lane];
        a0.x += v * x.x; a0.y += v * x.y; a0.z += v * x.z; a0.w += v * x.w;
    }
    float4 o;
    o.x = fmaxf(a0.x + a1.x + a2.x + a3.x, 0.f);
    o.y = fmaxf(a0.y + a1.y + a2.y + a3.y, 0.f);
    o.z = fmaxf(a0.z + a1.z + a2.z + a3.z, 0.f);
    o.w = fmaxf(a0.w + a1.w + a2.w + a3.w, 0.f);
    ((float4*)h2)[(size_t)node * 32 + lane] = o;
}

__global__ __launch_bounds__(256) void spmm2_warp_kernel(
    const float* __restrict__ h3, float* __restrict__ out) {
    int node = blockIdx.x * 8 + (threadIdx.x >> 5);
    int lane = threadIdx.x & 31;
    int s = g_rowptr[node], e = g_rowptr[node + 1];

    float2 a0 = make_float2(0.f, 0.f);
    float2 a1 = a0, a2 = a0, a3 = a0;
    const float2* H = (const float2*)h3;

    int j = s;
    for (; j + 7 < e; j += 8) {
        int2 e0 = g_edge[j],     e1 = g_edge[j + 1];
        int2 e2 = g_edge[j + 2], e3 = g_edge[j + 3];
        int2 e4 = g_edge[j + 4], e5 = g_edge[j + 5];
        int2 e6 = g_edge[j + 6], e7 = g_edge[j + 7];
        float2 x0 = H[(size_t)e0.x * 32 + lane];
        float2 x1 = H[(size_t)e1.x * 32 + lane];
        float2 x2 = H[(size_t)e2.x * 32 + lane];
        float2 x3 = H[(size_t)e3.x * 32 + lane];
        float2 x4 = H[(size_t)e4.x * 32 + lane];
        float2 x5 = H[(size_t)e5.x * 32 + lane];
        float2 x6 = H[(size_t)e6.x * 32 + lane];
        float2 x7 = H[(size_t)e7.x * 32 + lane];
        float v0 = __int_as_float(e0.y), v1 = __int_as_float(e1.y);
        float v2 = __int_as_float(e2.y), v3 = __int_as_float(e3.y);
        float v4 = __int_as_float(e4.y), v5 = __int_as_float(e5.y);
        float v6 = __int_as_float(e6.y), v7 = __int_as_float(e7.y);
        a0.x += v0 * x0.x; a0.y += v0 * x0.y;
        a1.x += v1 * x1.x; a1.y += v1 * x1.y;
        a2.x += v2 * x2.x; a2.y += v2 * x2.y;
        a3.x += v3 * x3.x; a3.y += v3 * x3.y;
        a0.x += v4 * x4.x; a0.y += v4 * x4.y;
        a1.x += v5 * x5.x; a1.y += v5 * x5.y;
        a2.x += v6 * x6.x; a2.y += v6 * x6.y;
        a3.x += v7 * x7.x; a3.y += v7 * x7.y;
    }
    for (; j + 3 < e; j += 4) {
        int2 e0 = g_edge[j],     e1 = g_edge[j + 1];
        int2 e2 = g_edge[j + 2], e3 = g_edge[j + 3];
        float v0 = __int_as_float(e0.y), v1 = __int_as_float(e1.y);
        float v2 = __int_as_float(e2.y), v3 = __int_as_float(e3.y);
        float2 x0 = H[(size_t)e0.x * 32 + lane];
        float2 x1 = H[(size_t)e1.x * 32 + lane];
        float2 x2 = H[(size_t)e2.x * 32 + lane];
        float2 x3 = H[(size_t)e3.x * 32 + lane];
        a0.x += v0 * x0.x; a0.y += v0 * x0.y;
        a1.x += v1 * x1.x; a1.y += v1 * x1.y;
        a2.x += v2 * x2.x; a2.y += v2 * x2.y;
        a3.x += v3 * x3.x; a3.y += v3 * x3.y;
    }
    for (; j < e; j++) {
        int2 ed = g_edge[j];
        float v = __int_as_float(ed.y);
        float2 x = H[(size_t)ed.x * 32 + lane];
        a0.x += v * x.x; a0.y += v * x.y;
    }
    float2 o;
    o.x = a0.x + a1.x + a2.x + a3.x;
    o.y = a0.y + a1.y + a2.y + a3.y;
    ((float2*)out)[(size_t)node * 32 + lane] = o;
}

// ---------------- launch ----------------
#define SMEM_PIPE(BN) (2 * 128 * LDA * 4 + 2 * (BN) * LDK * 2)

extern "C" void kernel_launch(void* const* d_in, const int* in_sizes, int n_in,
                              void* d_out, int out_size) {
    const float* x       = (const float*)d_in[0];
    const int*   adj_row = (const int*)d_in[1];
    const int*   adj_col = (const int*)d_in[2];
    const float* adj_val = (const float*)d_in[3];
    const float* w1      = (const float*)d_in[4];
    const float* b1      = (const float*)d_in[5];
    const float* w2      = (const float*)d_in[6];
    const float* b2      = (const float*)d_in[7];
    float* out = (float*)d_out;

    float* h1 = nullptr; float* h2 = nullptr; float* h3 = nullptr;
    const __nv_bfloat16 *w1h, *w1l, *w2h, *w2l;
    cudaGetSymbolAddress((void**)&h1, g_h1);
    cudaGetSymbolAddress((void**)&h2, g_h2);
    cudaGetSymbolAddress((void**)&h3, g_h3);
    cudaGetSymbolAddress((void**)&w1h, g_w1t_hi);
    cudaGetSymbolAddress((void**)&w1l, g_w1t_lo);
    cudaGetSymbolAddress((void**)&w2h, g_w2t_hi);
    cudaGetSymbolAddress((void**)&w2l, g_w2t_lo);

    static cudaStream_t s_side = nullptr;
    static cudaEvent_t ev_fork, ev_join, ev_g1, ev_l2;
    static bool init_done = false;
    if (!init_done) {
        cudaFuncSetAttribute(gemm_pipe_kernel<HID_F, IN_F>,
                             cudaFuncAttributeMaxDynamicSharedMemorySize, SMEM_PIPE(HID_F));
        cudaFuncSetAttribute(gemm_pipe_kernel<N_CLS, HID_F>,
                             cudaFuncAttributeMaxDynamicSharedMemorySize, SMEM_PIPE(N_CLS));
        cudaStreamCreateWithFlags(&s_side, cudaStreamNonBlocking);
        cudaEventCreateWithFlags(&ev_fork, cudaEventDisableTiming);
        cudaEventCreateWithFlags(&ev_join, cudaEventDisableTiming);
        cudaEventCreateWithFlags(&ev_g1,   cudaEventDisableTiming);
        cudaEventCreateWithFlags(&ev_l2,   cudaEventDisableTiming);
        init_done = true;
    }

    // ---- fork: side stream does prep_w2t + CSR build, concurrent with gemm1
    cudaEventRecord(ev_fork, 0);
    cudaStreamWaitEvent(s_side, ev_fork, 0);

    prep_w2t_kernel<<<(HID_F * N_CLS + 255) / 256, 256, 0, s_side>>>(w2);
    zero_deg_kernel<<<(N_NODES + 256) / 256, 256, 0, s_side>>>();
    count_kernel<<<(N_EDGES + 255) / 256, 256, 0, s_side>>>(adj_row);
    scan_kernel<<<1, 1024, 0, s_side>>>();
    scatter_kernel<<<(N_EDGES + 255) / 256, 256, 0, s_side>>>(adj_row, adj_col, adj_val);
    cudaEventRecord(ev_join, s_side);

    // ---- main stream: weight prep + gemm1 (all rows) ----
    prep_w1t_kernel<<<(IN_F * HID_F + 255) / 256, 256>>>(w1);
    gemm_pipe_kernel<HID_F, IN_F>
        <<<(N_NODES + 127) / 128, 256, SMEM_PIPE(HID_F)>>>(x, w1h, w1l, b1, h1, 0, N_NODES);
    cudaEventRecord(ev_g1, 0);

    // ---- layer-1 aggregation + layer-2 projection, split in halves ----
    cudaStreamWaitEvent(0, ev_join, 0);
    spmm1_warp_kernel<<<HALF_N / 8, 256>>>(h1, h2, 0);
    gemm_pipe_kernel<N_CLS, HID_F>
        <<<HALF_N / 128, 256, SMEM_PIPE(N_CLS)>>>(h2, w2h, w2l, b2, h3, 0, HALF_N);

    cudaStreamWaitEvent(s_side, ev_g1, 0);
    spmm1_warp_kernel<<<(N_NODES - HALF_N) / 8, 256, 0, s_side>>>(h1, h2, HALF_N);
    gemm_pipe_kernel<N_CLS, HID_F>
        <<<(N_NODES - HALF_N + 127) / 128, 256, SMEM_PIPE(N_CLS), s_side>>>(
            h2, w2h, w2l, b2, h3, HALF_N, N_NODES);
    cudaEventRecord(ev_l2, s_side);

    // ---- final aggregation (needs all h3) ----
    cudaStreamWaitEvent(0, ev_l2, 0);
    spmm2_warp_kernel<<<(N_NODES + 7) / 8, 256>>>(h3, out);
}

// round 15
// speedup vs baseline: 1.9571x; 1.9571x over previous
#include <cuda_runtime.h>
#include <cuda_bf16.h>
#include <cstdint>

#define N_NODES 100000
#define N_EDGES 1600000
#define IN_F    512
#define HID_F   128
#define N_CLS   64
#define HALF_N  50048            // split point, multiple of 128 and 8

// ---------------- device scratch (no allocations allowed) ----------------
__device__ __align__(16) float g_h1[(size_t)N_NODES * HID_F];
__device__ __align__(16) float g_h2[(size_t)N_NODES * HID_F];
__device__ __align__(16) float g_h3[(size_t)N_NODES * N_CLS];
__device__ int   g_deg[N_NODES + 1];
__device__ int   g_rowptr[N_NODES + 1];
__device__ int   g_fill[N_NODES];
__device__ int2  g_edge[N_EDGES];                 // {col, float_bits(val)}
__device__ __align__(16) __nv_bfloat16 g_w1t_hi[HID_F * IN_F];   // [128][512]
__device__ __align__(16) __nv_bfloat16 g_w1t_lo[HID_F * IN_F];
__device__ __align__(16) __nv_bfloat16 g_w2t_hi[N_CLS * HID_F];  // [64][128]
__device__ __align__(16) __nv_bfloat16 g_w2t_lo[N_CLS * HID_F];

// ---------------- small helpers ----------------
__device__ __forceinline__ uint32_t smem_u32(const void* p) {
    uint32_t a;
    asm("{ .reg .u64 t; cvta.to.shared.u64 t, %1; cvt.u32.u64 %0, t; }" : "=r"(a) : "l"(p));
    return a;
}
__device__ __forceinline__ void cp16(uint32_t dst, const void* src) {
    asm volatile("cp.async.ca.shared.global [%0], [%1], 16;" :: "r"(dst), "l"(src));
}
#define CP_COMMIT() asm volatile("cp.async.commit_group;" ::: "memory")
#define CP_WAIT(n)  asm volatile("cp.async.wait_group %0;" :: "n"(n) : "memory")

__device__ __forceinline__ void mma_bf16(float* c, const uint32_t* a, const uint32_t* b) {
    asm volatile(
        "mma.sync.aligned.m16n8k16.row.col.f32.bf16.bf16.f32 "
        "{%0,%1,%2,%3}, {%4,%5,%6,%7}, {%8,%9}, {%0,%1,%2,%3};"
        : "+f"(c[0]), "+f"(c[1]), "+f"(c[2]), "+f"(c[3])
        : "r"(a[0]), "r"(a[1]), "r"(a[2]), "r"(a[3]), "r"(b[0]), "r"(b[1]));
}
__device__ __forceinline__ uint32_t pack_bf16x2(__nv_bfloat16 a, __nv_bfloat16 b) {
    __nv_bfloat162 p; p.x = a; p.y = b;
    return *reinterpret_cast<uint32_t*>(&p);
}
// FAST split: hi = truncate-to-bf16 (exact top 16 bits), lo = rn(v - hi).
__device__ __forceinline__ uint32_t split2(float2 v, uint32_t& lo) {
    uint32_t u0 = __float_as_uint(v.x);
    uint32_t u1 = __float_as_uint(v.y);
    float l0 = v.x - __uint_as_float(u0 & 0xFFFF0000u);
    float l1 = v.y - __uint_as_float(u1 & 0xFFFF0000u);
    uint32_t hi, lou;
    asm("prmt.b32 %0, %1, %2, 0x7632;" : "=r"(hi) : "r"(u0), "r"(u1));
    asm("cvt.rn.bf16x2.f32 %0, %1, %2;" : "=r"(lou) : "f"(l1), "f"(l0));
    lo = lou;
    return hi;
}

// ---------------- CSR build ----------------
__global__ void zero_deg_kernel() {
    int i = blockIdx.x * blockDim.x + threadIdx.x;
    if (i <= N_NODES) g_deg[i] = 0;
}
__global__ void count_kernel(const int* __restrict__ row) {
    int e = blockIdx.x * blockDim.x + threadIdx.x;
    if (e < N_EDGES) atomicAdd(&g_deg[row[e]], 1);
}
// Coalesced tiled scan: tiles of 1024 contiguous elements, block scan per
// tile with a carried offset. All loads/stores coalesced; no dependent-load
// chain (the old contiguous-chunk-per-thread version cost ~155us).
__global__ __launch_bounds__(1024) void scan_kernel() {
    __shared__ int wsum[32];
    __shared__ int carry_s;
    int t = threadIdx.x, lane = t & 31, wid = t >> 5;
    if (t == 0) carry_s = 0;
    __syncthreads();

    const int NT = (N_NODES + 1023) / 1024;   // 98
    for (int tile = 0; tile < NT; tile++) {
        int i = tile * 1024 + t;
        int d = (i < N_NODES) ? g_deg[i] : 0;
        // warp inclusive scan
        int v = d;
#pragma unroll
        for (int o = 1; o < 32; o <<= 1) {
            int n = __shfl_up_sync(0xFFFFFFFF, v, o);
            if (lane >= o) v += n;
        }
        if (lane == 31) wsum[wid] = v;
        __syncthreads();
        if (wid == 0) {
            int w = wsum[lane];
#pragma unroll
            for (int o = 1; o < 32; o <<= 1) {
                int n = __shfl_up_sync(0xFFFFFFFF, w, o);
                if (lane >= o) w += n;
            }
            wsum[lane] = w;
        }
        __syncthreads();
        int excl = v - d + (wid ? wsum[wid - 1] : 0);
        int carry = carry_s;
        if (i < N_NODES) {
            g_rowptr[i] = carry + excl;
            g_fill[i]   = carry + excl;
        }
        __syncthreads();                       // all threads done reading carry_s
        if (t == 1023) carry_s = carry + excl + d;   // tile total (inclusive)
        __syncthreads();
    }
    if (t == 0) g_rowptr[N_NODES] = N_EDGES;
}
__global__ void scatter_kernel(const int* __restrict__ row, const int* __restrict__ col,
                               const float* __restrict__ val) {
    int e = blockIdx.x * blockDim.x + threadIdx.x;
    if (e < N_EDGES) {
        int r = row[e];
        int p = atomicAdd(&g_fill[r], 1);
        g_edge[p] = make_int2(col[e], __float_as_int(val[e]));
    }
}

// ---------------- weight prep: transpose + bf16 hi/lo split ----------------
__global__ void prep_w1t_kernel(const float* __restrict__ w1) {
    int idx = blockIdx.x * blockDim.x + threadIdx.x;
    if (idx < IN_F * HID_F) {
        int k = idx >> 7, n = idx & 127;
        float v = w1[idx];
        __nv_bfloat16 h = __float2bfloat16(v);
        float r = v - __bfloat162float(h);
        g_w1t_hi[n * IN_F + k] = h;
        g_w1t_lo[n * IN_F + k] = __float2bfloat16(r);
    }
}
__global__ void prep_w2t_kernel(const float* __restrict__ w2) {
    int idx = blockIdx.x * blockDim.x + threadIdx.x;
    if (idx < HID_F * N_CLS) {
        int k = idx >> 6, n = idx & 63;
        float v = w2[idx];
        __nv_bfloat16 h = __float2bfloat16(v);
        float r = v - __bfloat162float(h);
        g_w2t_hi[n * HID_F + k] = h;
        g_w2t_lo[n * HID_F + k] = __float2bfloat16(r);
    }
}

// ---------------- cp.async pipelined bf16-split GEMM (R7-proven) ------------
#define BK  64
#define LDK 72
#define LDA 68

template <int BN, int K_TOTAL>
__global__ __launch_bounds__(256) void gemm_pipe_kernel(
    const float* __restrict__ X,
    const __nv_bfloat16* __restrict__ Wt_hi,
    const __nv_bfloat16* __restrict__ Wt_lo,
    const float* __restrict__ Bias,
    float* __restrict__ O,
    int row_base, int row_limit) {
    constexpr int NITER = K_TOTAL / BK;
    extern __shared__ char smraw[];
    float* Af = (float*)smraw;                                   // [2][128][LDA]
    __nv_bfloat16* Bh = (__nv_bfloat16*)(Af + 2 * 128 * LDA);    // [BN][LDK]
    __nv_bfloat16* Bl = Bh + BN * LDK;

    const int t = threadIdx.x;
    const int lane = t & 31;
    const int wid = t >> 5;
    const int warp_m = wid & 3;
    const int warp_n = wid >> 2;
    const int NT = BN / 16;
    const int n0 = warp_n * (BN / 2);
    const int row0 = row_base + blockIdx.x * 128;
    const int gq = lane >> 2;
    const int gc2 = (lane & 3) * 2;

    const uint32_t af_u = smem_u32(Af);
    const uint32_t bh_u = smem_u32(Bh);
    const uint32_t bl_u = smem_u32(Bl);

    auto issueA = [&](int s) {
        const int buf = s & 1;
        const int k0 = s * BK;
#pragma unroll
        for (int i = 0; i < 8; i++) {
            int idx = t + i * 256;
            int row = idx >> 4, c4 = (idx & 15) * 4;
            int gr = row0 + row;
            if (gr >= N_NODES) gr = N_NODES - 1;
            cp16(af_u + (uint32_t)(((buf * 128 + row) * LDA + c4) * 4),
                 X + (size_t)gr * K_TOTAL + k0 + c4);
        }
    };
    auto issueB = [&](int s) {
        const int k0 = s * BK;
        constexpr int BCH = BN * 8 / 256;
#pragma unroll
        for (int i = 0; i < BCH; i++) {
            int idx = t + i * 256;
            int row = idx >> 3, q = (idx & 7) * 8;
            cp16(bh_u + (uint32_t)((row * LDK + q) * 2),
                 Wt_hi + (size_t)row * K_TOTAL + k0 + q);
            cp16(bl_u + (uint32_t)((row * LDK + q) * 2),
                 Wt_lo + (size_t)row * K_TOTAL + k0 + q);
        }
    };

    float acc[2][BN / 16][4];
#pragma unroll
    for (int mt = 0; mt < 2; mt++)
#pragma unroll
        for (int nt = 0; nt < NT; nt++)
#pragma unroll
            for (int i = 0; i < 4; i++) acc[mt][nt][i] = 0.f;

    issueB(0); CP_COMMIT();
    issueA(0); CP_COMMIT();
    if (NITER > 1) { issueA(1); CP_COMMIT(); CP_WAIT(1); }
    else           { CP_WAIT(0); }
    __syncthreads();

    for (int c = 0; c < NITER; c++) {
        const int buf = c & 1;
#pragma unroll
        for (int ks = 0; ks < 4; ks++) {
            const int k = ks * 16;
            uint32_t ah[2][4], al[2][4];
#pragma unroll
            for (int mt = 0; mt < 2; mt++) {
                const int rb = buf * 128 + warp_m * 32 + mt * 16 + gq;
                const float* p0 = &Af[rb * LDA + k + gc2];
                float2 v0 = *(const float2*)(p0);
                float2 v1 = *(const float2*)(p0 + 8 * LDA);
                float2 v2 = *(const float2*)(p0 + 8);
                float2 v3 = *(const float2*)(p0 + 8 * LDA + 8);
                ah[mt][0] = split2(v0, al[mt][0]);
                ah[mt][1] = split2(v1, al[mt][1]);
                ah[mt][2] = split2(v2, al[mt][2]);
                ah[mt][3] = split2(v3, al[mt][3]);
            }
#pragma unroll
            for (int nt = 0; nt < NT; nt++) {
                const int nrow = n0 + nt * 8 + gq;
                const __nv_bfloat16* ph = &Bh[nrow * LDK + k + gc2];
                const __nv_bfloat16* pl = &Bl[nrow * LDK + k + gc2];
                uint32_t bh[2], bl[2];
                bh[0] = *(const uint32_t*)(ph);
                bh[1] = *(const uint32_t*)(ph + 8);
                bl[0] = *(const uint32_t*)(pl);
                bl[1] = *(const uint32_t*)(pl + 8);
#pragma unroll
                for (int mt = 0; mt < 2; mt++) {
                    mma_bf16(acc[mt][nt], ah[mt], bh);
                    mma_bf16(acc[mt][nt], ah[mt], bl);
                    mma_bf16(acc[mt][nt], al[mt], bh);
                }
            }
        }
        __syncthreads();
        if (c + 1 < NITER) {
            issueB(c + 1); CP_COMMIT();
            if (c + 2 < NITER) { issueA(c + 2); CP_COMMIT(); CP_WAIT(1); }
            else               { CP_WAIT(0); }
            __syncthreads();
        }
    }

#pragma unroll
    for (int nt = 0; nt < NT; nt++) {
        const int colb = n0 + nt * 8 + gc2;
        float2 bb = *(const float2*)&Bias[colb];
#pragma unroll
        for (int mt = 0; mt < 2; mt++) {
            int r0 = row0 + warp_m * 32 + mt * 16 + gq;
            if (r0 < row_limit) {
                float2 o0;
                o0.x = acc[mt][nt][0] + bb.x;
                o0.y = acc[mt][nt][1] + bb.y;
                *(float2*)&O[(size_t)r0 * BN + colb] = o0;
            }
            int r1 = r0 + 8;
            if (r1 < row_limit) {
                float2 o1;
                o1.x = acc[mt][nt][2] + bb.x;
                o1.y = acc[mt][nt][3] + bb.y;
                *(float2*)&O[(size_t)r1 * BN + colb] = o1;
            }
        }
    }
}

// ---------------- SpMM: warp-per-node, 4-edge unroll (R13-proven) -----------
__global__ __launch_bounds__(256) void spmm1_warp_kernel(
    const float* __restrict__ h1, float* __restrict__ h2, int node_base) {
    int node = node_base + blockIdx.x * 8 + (threadIdx.x >> 5);
    int lane = threadIdx.x & 31;
    int s = g_rowptr[node], e = g_rowptr[node + 1];

    float4 a0 = make_float4(0.f, 0.f, 0.f, 0.f);
    float4 a1 = a0, a2 = a0, a3 = a0;
    const float4* H = (const float4*)h1;

    int j = s;
    for (; j + 3 < e; j += 4) {
        int2 e0 = g_edge[j],     e1 = g_edge[j + 1];
        int2 e2 = g_edge[j + 2], e3 = g_edge[j + 3];
        float v0 = __int_as_float(e0.y), v1 = __int_as_float(e1.y);
        float v2 = __int_as_float(e2.y), v3 = __int_as_float(e3.y);
        float4 x0 = H[(size_t)e0.x * 32 + lane];
        float4 x1 = H[(size_t)e1.x * 32 + lane];
        float4 x2 = H[(size_t)e2.x * 32 + lane];
        float4 x3 = H[(size_t)e3.x * 32 + lane];
        a0.x += v0 * x0.x; a0.y += v0 * x0.y; a0.z += v0 * x0.z; a0.w += v0 * x0.w;
        a1.x += v1 * x1.x; a1.y += v1 * x1.y; a1.z += v1 * x1.z; a1.w += v1 * x1.w;
        a2.x += v2 * x2.x; a2.y += v2 * x2.y; a2.z += v2 * x2.z; a2.w += v2 * x2.w;
        a3.x += v3 * x3.x; a3.y += v3 * x3.y; a3.z += v3 * x3.z; a3.w += v3 * x3.w;
    }
    for (; j < e; j++) {
        int2 ed = g_edge[j];
        float v = __int_as_float(ed.y);
        float4 x = H[(size_t)ed.x * 32 + lane];
        a0.x += v * x.x; a0.y += v * x.y; a0.z += v * x.z; a0.w += v * x.w;
    }
    float4 o;
    o.x = fmaxf(a0.x + a1.x + a2.x + a3.x, 0.f);
    o.y = fmaxf(a0.y + a1.y + a2.y + a3.y, 0.f);
    o.z = fmaxf(a0.z + a1.z + a2.z + a3.z, 0.f);
    o.w = fmaxf(a0.w + a1.w + a2.w + a3.w, 0.f);
    ((float4*)h2)[(size_t)node * 32 + lane] = o;
}

__global__ __launch_bounds__(256) void spmm2_warp_kernel(
    const float* __restrict__ h3, float* __restrict__ out) {
    int node = blockIdx.x * 8 + (threadIdx.x >> 5);
    int lane = threadIdx.x & 31;
    int s = g_rowptr[node], e = g_rowptr[node + 1];

    float2 a0 = make_float2(0.f, 0.f);
    float2 a1 = a0, a2 = a0, a3 = a0;
    const float2* H = (const float2*)h3;

    int j = s;
    for (; j + 3 < e; j += 4) {
        int2 e0 = g_edge[j],     e1 = g_edge[j + 1];
        int2 e2 = g_edge[j + 2], e3 = g_edge[j + 3];
        float v0 = __int_as_float(e0.y), v1 = __int_as_float(e1.y);
        float v2 = __int_as_float(e2.y), v3 = __int_as_float(e3.y);
        float2 x0 = H[(size_t)e0.x * 32 + lane];
        float2 x1 = H[(size_t)e1.x * 32 + lane];
        float2 x2 = H[(size_t)e2.x * 32 + lane];
        float2 x3 = H[(size_t)e3.x * 32 + lane];
        a0.x += v0 * x0.x; a0.y += v0 * x0.y;
        a1.x += v1 * x1.x; a1.y += v1 * x1.y;
        a2.x += v2 * x2.x; a2.y += v2 * x2.y;
        a3.x += v3 * x3.x; a3.y += v3 * x3.y;
    }
    for (; j < e; j++) {
        int2 ed = g_edge[j];
        float v = __int_as_float(ed.y);
        float2 x = H[(size_t)ed.x * 32 + lane];
        a0.x += v * x.x; a0.y += v * x.y;
    }
    float2 o;
    o.x = a0.x + a1.x + a2.x + a3.x;
    o.y = a0.y + a1.y + a2.y + a3.y;
    ((float2*)out)[(size_t)node * 32 + lane] = o;
}

// ---------------- launch ----------------
#define SMEM_PIPE(BN) (2 * 128 * LDA * 4 + 2 * (BN) * LDK * 2)

extern "C" void kernel_launch(void* const* d_in, const int* in_sizes, int n_in,
                              void* d_out, int out_size) {
    const float* x       = (const float*)d_in[0];
    const int*   adj_row = (const int*)d_in[1];
    const int*   adj_col = (const int*)d_in[2];
    const float* adj_val = (const float*)d_in[3];
    const float* w1      = (const float*)d_in[4];
    const float* b1      = (const float*)d_in[5];
    const float* w2      = (const float*)d_in[6];
    const float* b2      = (const float*)d_in[7];
    float* out = (float*)d_out;

    float* h1 = nullptr; float* h2 = nullptr; float* h3 = nullptr;
    const __nv_bfloat16 *w1h, *w1l, *w2h, *w2l;
    cudaGetSymbolAddress((void**)&h1, g_h1);
    cudaGetSymbolAddress((void**)&h2, g_h2);
    cudaGetSymbolAddress((void**)&h3, g_h3);
    cudaGetSymbolAddress((void**)&w1h, g_w1t_hi);
    cudaGetSymbolAddress((void**)&w1l, g_w1t_lo);
    cudaGetSymbolAddress((void**)&w2h, g_w2t_hi);
    cudaGetSymbolAddress((void**)&w2l, g_w2t_lo);

    static cudaStream_t s_side = nullptr;
    static cudaEvent_t ev_fork, ev_join, ev_g1, ev_l2;
    static bool init_done = false;
    if (!init_done) {
        cudaFuncSetAttribute(gemm_pipe_kernel<HID_F, IN_F>,
                             cudaFuncAttributeMaxDynamicSharedMemorySize, SMEM_PIPE(HID_F));
        cudaFuncSetAttribute(gemm_pipe_kernel<N_CLS, HID_F>,
                             cudaFuncAttributeMaxDynamicSharedMemorySize, SMEM_PIPE(N_CLS));
        cudaStreamCreateWithFlags(&s_side, cudaStreamNonBlocking);
        cudaEventCreateWithFlags(&ev_fork, cudaEventDisableTiming);
        cudaEventCreateWithFlags(&ev_join, cudaEventDisableTiming);
        cudaEventCreateWithFlags(&ev_g1,   cudaEventDisableTiming);
        cudaEventCreateWithFlags(&ev_l2,   cudaEventDisableTiming);
        init_done = true;
    }

    // ---- fork: CSR build on side stream, concurrent with prep + gemm1 ----
    cudaEventRecord(ev_fork, 0);
    cudaStreamWaitEvent(s_side, ev_fork, 0);

    zero_deg_kernel<<<(N_NODES + 256) / 256, 256, 0, s_side>>>();
    count_kernel<<<(N_EDGES + 255) / 256, 256, 0, s_side>>>(adj_row);
    scan_kernel<<<1, 1024, 0, s_side>>>();
    scatter_kernel<<<(N_EDGES + 255) / 256, 256, 0, s_side>>>(adj_row, adj_col, adj_val);
    cudaEventRecord(ev_join, s_side);

    // ---- main stream: weight prep + gemm1 (all rows) ----
    prep_w1t_kernel<<<(IN_F * HID_F + 255) / 256, 256>>>(w1);
    prep_w2t_kernel<<<(HID_F * N_CLS + 255) / 256, 256>>>(w2);
    gemm_pipe_kernel<HID_F, IN_F>
        <<<(N_NODES + 127) / 128, 256, SMEM_PIPE(HID_F)>>>(x, w1h, w1l, b1, h1, 0, N_NODES);
    cudaEventRecord(ev_g1, 0);

    // ---- layer-1 aggregation + layer-2 projection, split in halves ----
    cudaStreamWaitEvent(0, ev_join, 0);
    spmm1_warp_kernel<<<HALF_N / 8, 256>>>(h1, h2, 0);
    gemm_pipe_kernel<N_CLS, HID_F>
        <<<HALF_N / 128, 256, SMEM_PIPE(N_CLS)>>>(h2, w2h, w2l, b2, h3, 0, HALF_N);

    cudaStreamWaitEvent(s_side, ev_g1, 0);
    spmm1_warp_kernel<<<(N_NODES - HALF_N) / 8, 256, 0, s_side>>>(h1, h2, HALF_N);
    gemm_pipe_kernel<N_CLS, HID_F>
        <<<(N_NODES - HALF_N + 127) / 128, 256, SMEM_PIPE(N_CLS), s_side>>>(
            h2, w2h, w2l, b2, h3, HALF_N, N_NODES);
    cudaEventRecord(ev_l2, s_side);

    // ---- final aggregation (needs all h3) ----
    cudaStreamWaitEvent(0, ev_l2, 0);
    spmm2_warp_kernel<<<(N_NODES + 7) / 8, 256>>>(h3, out);
}

// round 16
// speedup vs baseline: 2.0617x; 1.0535x over previous
#include <cuda_runtime.h>
#include <cuda_bf16.h>
#include <cuda_fp16.h>
#include <cstdint>

#define N_NODES 100000
#define N_EDGES 1600000
#define IN_F    512
#define HID_F   128
#define N_CLS   64
#define HALF_N  50048            // split point, multiple of 128 and 8

// ---------------- device scratch (no allocations allowed) ----------------
__device__ __align__(16) __half g_h1[(size_t)N_NODES * HID_F];   // fp16 h1
__device__ __align__(16) float  g_h2[(size_t)N_NODES * HID_F];
__device__ __align__(16) __half g_h3[(size_t)N_NODES * N_CLS];   // fp16 h3
__device__ int   g_deg[N_NODES + 1];
__device__ int   g_rowptr[N_NODES + 1];
__device__ int   g_fill[N_NODES];
__device__ int2  g_edge[N_EDGES];                 // {col, float_bits(val)}
__device__ __align__(16) __nv_bfloat16 g_w1t_hi[HID_F * IN_F];   // [128][512]
__device__ __align__(16) __nv_bfloat16 g_w1t_lo[HID_F * IN_F];
__device__ __align__(16) __nv_bfloat16 g_w2t_hi[N_CLS * HID_F];  // [64][128]
__device__ __align__(16) __nv_bfloat16 g_w2t_lo[N_CLS * HID_F];

// ---------------- small helpers ----------------
__device__ __forceinline__ uint32_t smem_u32(const void* p) {
    uint32_t a;
    asm("{ .reg .u64 t; cvta.to.shared.u64 t, %1; cvt.u32.u64 %0, t; }" : "=r"(a) : "l"(p));
    return a;
}
__device__ __forceinline__ void cp16(uint32_t dst, const void* src) {
    asm volatile("cp.async.ca.shared.global [%0], [%1], 16;" :: "r"(dst), "l"(src));
}
#define CP_COMMIT() asm volatile("cp.async.commit_group;" ::: "memory")
#define CP_WAIT(n)  asm volatile("cp.async.wait_group %0;" :: "n"(n) : "memory")

__device__ __forceinline__ void mma_bf16(float* c, const uint32_t* a, const uint32_t* b) {
    asm volatile(
        "mma.sync.aligned.m16n8k16.row.col.f32.bf16.bf16.f32 "
        "{%0,%1,%2,%3}, {%4,%5,%6,%7}, {%8,%9}, {%0,%1,%2,%3};"
        : "+f"(c[0]), "+f"(c[1]), "+f"(c[2]), "+f"(c[3])
        : "r"(a[0]), "r"(a[1]), "r"(a[2]), "r"(a[3]), "r"(b[0]), "r"(b[1]));
}
__device__ __forceinline__ uint32_t pack_bf16x2(__nv_bfloat16 a, __nv_bfloat16 b) {
    __nv_bfloat162 p; p.x = a; p.y = b;
    return *reinterpret_cast<uint32_t*>(&p);
}
// FAST split: hi = truncate-to-bf16 (exact top 16 bits), lo = rn(v - hi).
__device__ __forceinline__ uint32_t split2(float2 v, uint32_t& lo) {
    uint32_t u0 = __float_as_uint(v.x);
    uint32_t u1 = __float_as_uint(v.y);
    float l0 = v.x - __uint_as_float(u0 & 0xFFFF0000u);
    float l1 = v.y - __uint_as_float(u1 & 0xFFFF0000u);
    uint32_t hi, lou;
    asm("prmt.b32 %0, %1, %2, 0x7632;" : "=r"(hi) : "r"(u0), "r"(u1));
    asm("cvt.rn.bf16x2.f32 %0, %1, %2;" : "=r"(lou) : "f"(l1), "f"(l0));
    lo = lou;
    return hi;
}

// ---------------- CSR build ----------------
__global__ void zero_deg_kernel() {
    int i = blockIdx.x * blockDim.x + threadIdx.x;
    if (i <= N_NODES) g_deg[i] = 0;
}
__global__ void count_kernel(const int* __restrict__ row) {
    int e = blockIdx.x * blockDim.x + threadIdx.x;
    if (e < N_EDGES) atomicAdd(&g_deg[row[e]], 1);
}
// Coalesced tiled scan (R15-proven).
__global__ __launch_bounds__(1024) void scan_kernel() {
    __shared__ int wsum[32];
    __shared__ int carry_s;
    int t = threadIdx.x, lane = t & 31, wid = t >> 5;
    if (t == 0) carry_s = 0;
    __syncthreads();

    const int NT = (N_NODES + 1023) / 1024;   // 98
    for (int tile = 0; tile < NT; tile++) {
        int i = tile * 1024 + t;
        int d = (i < N_NODES) ? g_deg[i] : 0;
        int v = d;
#pragma unroll
        for (int o = 1; o < 32; o <<= 1) {
            int n = __shfl_up_sync(0xFFFFFFFF, v, o);
            if (lane >= o) v += n;
        }
        if (lane == 31) wsum[wid] = v;
        __syncthreads();
        if (wid == 0) {
            int w = wsum[lane];
#pragma unroll
            for (int o = 1; o < 32; o <<= 1) {
                int n = __shfl_up_sync(0xFFFFFFFF, w, o);
                if (lane >= o) w += n;
            }
            wsum[lane] = w;
        }
        __syncthreads();
        int excl = v - d + (wid ? wsum[wid - 1] : 0);
        int carry = carry_s;
        if (i < N_NODES) {
            g_rowptr[i] = carry + excl;
            g_fill[i]   = carry + excl;
        }
        __syncthreads();
        if (t == 1023) carry_s = carry + excl + d;
        __syncthreads();
    }
    if (t == 0) g_rowptr[N_NODES] = N_EDGES;
}
__global__ void scatter_kernel(const int* __restrict__ row, const int* __restrict__ col,
                               const float* __restrict__ val) {
    int e = blockIdx.x * blockDim.x + threadIdx.x;
    if (e < N_EDGES) {
        int r = row[e];
        int p = atomicAdd(&g_fill[r], 1);
        g_edge[p] = make_int2(col[e], __float_as_int(val[e]));
    }
}

// ---------------- weight prep: transpose + bf16 hi/lo split ----------------
__global__ void prep_w1t_kernel(const float* __restrict__ w1) {
    int idx = blockIdx.x * blockDim.x + threadIdx.x;
    if (idx < IN_F * HID_F) {
        int k = idx >> 7, n = idx & 127;
        float v = w1[idx];
        __nv_bfloat16 h = __float2bfloat16(v);
        float r = v - __bfloat162float(h);
        g_w1t_hi[n * IN_F + k] = h;
        g_w1t_lo[n * IN_F + k] = __float2bfloat16(r);
    }
}
__global__ void prep_w2t_kernel(const float* __restrict__ w2) {
    int idx = blockIdx.x * blockDim.x + threadIdx.x;
    if (idx < HID_F * N_CLS) {
        int k = idx >> 6, n = idx & 63;
        float v = w2[idx];
        __nv_bfloat16 h = __float2bfloat16(v);
        float r = v - __bfloat162float(h);
        g_w2t_hi[n * HID_F + k] = h;
        g_w2t_lo[n * HID_F + k] = __float2bfloat16(r);
    }
}

// ---------------- cp.async pipelined bf16-split GEMM ------------------------
// HALF_OUT: epilogue writes __half output (packed half2) instead of fp32.
#define BK  64
#define LDK 72
#define LDA 68

template <int BN, int K_TOTAL>
__global__ __launch_bounds__(256) void gemm_pipe_kernel(
    const float* __restrict__ X,
    const __nv_bfloat16* __restrict__ Wt_hi,
    const __nv_bfloat16* __restrict__ Wt_lo,
    const float* __restrict__ Bias,
    __half* __restrict__ O,
    int row_base, int row_limit) {
    constexpr int NITER = K_TOTAL / BK;
    extern __shared__ char smraw[];
    float* Af = (float*)smraw;                                   // [2][128][LDA]
    __nv_bfloat16* Bh = (__nv_bfloat16*)(Af + 2 * 128 * LDA);    // [BN][LDK]
    __nv_bfloat16* Bl = Bh + BN * LDK;

    const int t = threadIdx.x;
    const int lane = t & 31;
    const int wid = t >> 5;
    const int warp_m = wid & 3;
    const int warp_n = wid >> 2;
    const int NT = BN / 16;
    const int n0 = warp_n * (BN / 2);
    const int row0 = row_base + blockIdx.x * 128;
    const int gq = lane >> 2;
    const int gc2 = (lane & 3) * 2;

    const uint32_t af_u = smem_u32(Af);
    const uint32_t bh_u = smem_u32(Bh);
    const uint32_t bl_u = smem_u32(Bl);

    auto issueA = [&](int s) {
        const int buf = s & 1;
        const int k0 = s * BK;
#pragma unroll
        for (int i = 0; i < 8; i++) {
            int idx = t + i * 256;
            int row = idx >> 4, c4 = (idx & 15) * 4;
            int gr = row0 + row;
            if (gr >= N_NODES) gr = N_NODES - 1;
            cp16(af_u + (uint32_t)(((buf * 128 + row) * LDA + c4) * 4),
                 X + (size_t)gr * K_TOTAL + k0 + c4);
        }
    };
    auto issueB = [&](int s) {
        const int k0 = s * BK;
        constexpr int BCH = BN * 8 / 256;
#pragma unroll
        for (int i = 0; i < BCH; i++) {
            int idx = t + i * 256;
            int row = idx >> 3, q = (idx & 7) * 8;
            cp16(bh_u + (uint32_t)((row * LDK + q) * 2),
                 Wt_hi + (size_t)row * K_TOTAL + k0 + q);
            cp16(bl_u + (uint32_t)((row * LDK + q) * 2),
                 Wt_lo + (size_t)row * K_TOTAL + k0 + q);
        }
    };

    float acc[2][BN / 16][4];
#pragma unroll
    for (int mt = 0; mt < 2; mt++)
#pragma unroll
        for (int nt = 0; nt < NT; nt++)
#pragma unroll
            for (int i = 0; i < 4; i++) acc[mt][nt][i] = 0.f;

    issueB(0); CP_COMMIT();
    issueA(0); CP_COMMIT();
    if (NITER > 1) { issueA(1); CP_COMMIT(); CP_WAIT(1); }
    else           { CP_WAIT(0); }
    __syncthreads();

    for (int c = 0; c < NITER; c++) {
        const int buf = c & 1;
#pragma unroll
        for (int ks = 0; ks < 4; ks++) {
            const int k = ks * 16;
            uint32_t ah[2][4], al[2][4];
#pragma unroll
            for (int mt = 0; mt < 2; mt++) {
                const int rb = buf * 128 + warp_m * 32 + mt * 16 + gq;
                const float* p0 = &Af[rb * LDA + k + gc2];
                float2 v0 = *(const float2*)(p0);
                float2 v1 = *(const float2*)(p0 + 8 * LDA);
                float2 v2 = *(const float2*)(p0 + 8);
                float2 v3 = *(const float2*)(p0 + 8 * LDA + 8);
                ah[mt][0] = split2(v0, al[mt][0]);
                ah[mt][1] = split2(v1, al[mt][1]);
                ah[mt][2] = split2(v2, al[mt][2]);
                ah[mt][3] = split2(v3, al[mt][3]);
            }
#pragma unroll
            for (int nt = 0; nt < NT; nt++) {
                const int nrow = n0 + nt * 8 + gq;
                const __nv_bfloat16* ph = &Bh[nrow * LDK + k + gc2];
                const __nv_bfloat16* pl = &Bl[nrow * LDK + k + gc2];
                uint32_t bh[2], bl[2];
                bh[0] = *(const uint32_t*)(ph);
                bh[1] = *(const uint32_t*)(ph + 8);
                bl[0] = *(const uint32_t*)(pl);
                bl[1] = *(const uint32_t*)(pl + 8);
#pragma unroll
                for (int mt = 0; mt < 2; mt++) {
                    mma_bf16(acc[mt][nt], ah[mt], bh);
                    mma_bf16(acc[mt][nt], ah[mt], bl);
                    mma_bf16(acc[mt][nt], al[mt], bh);
                }
            }
        }
        __syncthreads();
        if (c + 1 < NITER) {
            issueB(c + 1); CP_COMMIT();
            if (c + 2 < NITER) { issueA(c + 2); CP_COMMIT(); CP_WAIT(1); }
            else               { CP_WAIT(0); }
            __syncthreads();
        }
    }

#pragma unroll
    for (int nt = 0; nt < NT; nt++) {
        const int colb = n0 + nt * 8 + gc2;
        float2 bb = *(const float2*)&Bias[colb];
#pragma unroll
        for (int mt = 0; mt < 2; mt++) {
            int r0 = row0 + warp_m * 32 + mt * 16 + gq;
            if (r0 < row_limit) {
                __half2 h = __floats2half2_rn(acc[mt][nt][0] + bb.x,
                                              acc[mt][nt][1] + bb.y);
                *(__half2*)(O + (size_t)r0 * BN + colb) = h;
            }
            int r1 = r0 + 8;
            if (r1 < row_limit) {
                __half2 h = __floats2half2_rn(acc[mt][nt][2] + bb.x,
                                              acc[mt][nt][3] + bb.y);
                *(__half2*)(O + (size_t)r1 * BN + colb) = h;
            }
        }
    }
}

// ---------------- SpMM1: fp16 h1 gather (256B/edge), fp32 h2 out ------------
__global__ __launch_bounds__(256) void spmm1_warp_kernel(
    const __half* __restrict__ h1, float* __restrict__ h2, int node_base) {
    int node = node_base + blockIdx.x * 8 + (threadIdx.x >> 5);
    int lane = threadIdx.x & 31;
    int s = g_rowptr[node], e = g_rowptr[node + 1];

    float4 a0 = make_float4(0.f, 0.f, 0.f, 0.f);
    float4 a1 = a0, a2 = a0, a3 = a0;
    const uint2* H = (const uint2*)h1;     // 4 halves per lane

    auto fma4 = [&](float4& a, float v, uint2 u) {
        float2 f0 = __half22float2(*(__half2*)&u.x);
        float2 f1 = __half22float2(*(__half2*)&u.y);
        a.x += v * f0.x; a.y += v * f0.y;
        a.z += v * f1.x; a.w += v * f1.y;
    };

    int j = s;
    for (; j + 3 < e; j += 4) {
        int2 e0 = g_edge[j],     e1 = g_edge[j + 1];
        int2 e2 = g_edge[j + 2], e3 = g_edge[j + 3];
        uint2 x0 = H[(size_t)e0.x * 32 + lane];
        uint2 x1 = H[(size_t)e1.x * 32 + lane];
        uint2 x2 = H[(size_t)e2.x * 32 + lane];
        uint2 x3 = H[(size_t)e3.x * 32 + lane];
        fma4(a0, __int_as_float(e0.y), x0);
        fma4(a1, __int_as_float(e1.y), x1);
        fma4(a2, __int_as_float(e2.y), x2);
        fma4(a3, __int_as_float(e3.y), x3);
    }
    for (; j < e; j++) {
        int2 ed = g_edge[j];
        uint2 x = H[(size_t)ed.x * 32 + lane];
        fma4(a0, __int_as_float(ed.y), x);
    }
    float4 o;
    o.x = fmaxf(a0.x + a1.x + a2.x + a3.x, 0.f);
    o.y = fmaxf(a0.y + a1.y + a2.y + a3.y, 0.f);
    o.z = fmaxf(a0.z + a1.z + a2.z + a3.z, 0.f);
    o.w = fmaxf(a0.w + a1.w + a2.w + a3.w, 0.f);
    ((float4*)h2)[(size_t)node * 32 + lane] = o;
}

// ---------------- SpMM2: fp16 h3 gather (128B/edge), fp32 out ---------------
__global__ __launch_bounds__(256) void spmm2_warp_kernel(
    const __half* __restrict__ h3, float* __restrict__ out) {
    int node = blockIdx.x * 8 + (threadIdx.x >> 5);
    int lane = threadIdx.x & 31;
    int s = g_rowptr[node], e = g_rowptr[node + 1];

    float2 a0 = make_float2(0.f, 0.f);
    float2 a1 = a0, a2 = a0, a3 = a0;
    const uint32_t* H = (const uint32_t*)h3;   // 2 halves per lane

    auto fma2 = [&](float2& a, float v, uint32_t u) {
        float2 f = __half22float2(*(__half2*)&u);
        a.x += v * f.x; a.y += v * f.y;
    };

    int j = s;
    for (; j + 3 < e; j += 4) {
        int2 e0 = g_edge[j],     e1 = g_edge[j + 1];
        int2 e2 = g_edge[j + 2], e3 = g_edge[j + 3];
        uint32_t x0 = H[(size_t)e0.x * 32 + lane];
        uint32_t x1 = H[(size_t)e1.x * 32 + lane];
        uint32_t x2 = H[(size_t)e2.x * 32 + lane];
        uint32_t x3 = H[(size_t)e3.x * 32 + lane];
        fma2(a0, __int_as_float(e0.y), x0);
        fma2(a1, __int_as_float(e1.y), x1);
        fma2(a2, __int_as_float(e2.y), x2);
        fma2(a3, __int_as_float(e3.y), x3);
    }
    for (; j < e; j++) {
        int2 ed = g_edge[j];
        uint32_t x = H[(size_t)ed.x * 32 + lane];
        fma2(a0, __int_as_float(ed.y), x);
    }
    float2 o;
    o.x = a0.x + a1.x + a2.x + a3.x;
    o.y = a0.y + a1.y + a2.y + a3.y;
    ((float2*)out)[(size_t)node * 32 + lane] = o;
}

// ---------------- launch ----------------
#define SMEM_PIPE(BN) (2 * 128 * LDA * 4 + 2 * (BN) * LDK * 2)

extern "C" void kernel_launch(void* const* d_in, const int* in_sizes, int n_in,
                              void* d_out, int out_size) {
    const float* x       = (const float*)d_in[0];
    const int*   adj_row = (const int*)d_in[1];
    const int*   adj_col = (const int*)d_in[2];
    const float* adj_val = (const float*)d_in[3];
    const float* w1      = (const float*)d_in[4];
    const float* b1      = (const float*)d_in[5];
    const float* w2      = (const float*)d_in[6];
    const float* b2      = (const float*)d_in[7];
    float* out = (float*)d_out;

    __half* h1 = nullptr; float* h2 = nullptr; __half* h3 = nullptr;
    const __nv_bfloat16 *w1h, *w1l, *w2h, *w2l;
    cudaGetSymbolAddress((void**)&h1, g_h1);
    cudaGetSymbolAddress((void**)&h2, g_h2);
    cudaGetSymbolAddress((void**)&h3, g_h3);
    cudaGetSymbolAddress((void**)&w1h, g_w1t_hi);
    cudaGetSymbolAddress((void**)&w1l, g_w1t_lo);
    cudaGetSymbolAddress((void**)&w2h, g_w2t_hi);
    cudaGetSymbolAddress((void**)&w2l, g_w2t_lo);

    static cudaStream_t s_side = nullptr;
    static cudaEvent_t ev_fork, ev_join, ev_g1, ev_l2;
    static bool init_done = false;
    if (!init_done) {
        cudaFuncSetAttribute(gemm_pipe_kernel<HID_F, IN_F>,
                             cudaFuncAttributeMaxDynamicSharedMemorySize, SMEM_PIPE(HID_F));
        cudaFuncSetAttribute(gemm_pipe_kernel<N_CLS, HID_F>,
                             cudaFuncAttributeMaxDynamicSharedMemorySize, SMEM_PIPE(N_CLS));
        cudaStreamCreateWithFlags(&s_side, cudaStreamNonBlocking);
        cudaEventCreateWithFlags(&ev_fork, cudaEventDisableTiming);
        cudaEventCreateWithFlags(&ev_join, cudaEventDisableTiming);
        cudaEventCreateWithFlags(&ev_g1,   cudaEventDisableTiming);
        cudaEventCreateWithFlags(&ev_l2,   cudaEventDisableTiming);
        init_done = true;
    }

    // ---- fork: CSR build on side stream, concurrent with prep + gemm1 ----
    cudaEventRecord(ev_fork, 0);
    cudaStreamWaitEvent(s_side, ev_fork, 0);

    zero_deg_kernel<<<(N_NODES + 256) / 256, 256, 0, s_side>>>();
    count_kernel<<<(N_EDGES + 255) / 256, 256, 0, s_side>>>(adj_row);
    scan_kernel<<<1, 1024, 0, s_side>>>();
    scatter_kernel<<<(N_EDGES + 255) / 256, 256, 0, s_side>>>(adj_row, adj_col, adj_val);
    cudaEventRecord(ev_join, s_side);

    // ---- main stream: weight prep + gemm1 (all rows) ----
    prep_w1t_kernel<<<(IN_F * HID_F + 255) / 256, 256>>>(w1);
    prep_w2t_kernel<<<(HID_F * N_CLS + 255) / 256, 256>>>(w2);
    gemm_pipe_kernel<HID_F, IN_F>
        <<<(N_NODES + 127) / 128, 256, SMEM_PIPE(HID_F)>>>(x, w1h, w1l, b1, h1, 0, N_NODES);
    cudaEventRecord(ev_g1, 0);

    // ---- layer-1 aggregation + layer-2 projection, split in halves ----
    cudaStreamWaitEvent(0, ev_join, 0);
    spmm1_warp_kernel<<<HALF_N / 8, 256>>>(h1, h2, 0);
    gemm_pipe_kernel<N_CLS, HID_F>
        <<<HALF_N / 128, 256, SMEM_PIPE(N_CLS)>>>(h2, w2h, w2l, b2, h3, 0, HALF_N);

    cudaStreamWaitEvent(s_side, ev_g1, 0);
    spmm1_warp_kernel<<<(N_NODES - HALF_N) / 8, 256, 0, s_side>>>(h1, h2, HALF_N);
    gemm_pipe_kernel<N_CLS, HID_F>
        <<<(N_NODES - HALF_N + 127) / 128, 256, SMEM_PIPE(N_CLS), s_side>>>(
            h2, w2h, w2l, b2, h3, HALF_N, N_NODES);
    cudaEventRecord(ev_l2, s_side);

    // ---- final aggregation (needs all h3) ----
    cudaStreamWaitEvent(0, ev_l2, 0);
    spmm2_warp_kernel<<<(N_NODES + 7) / 8, 256>>>(h3, out);
}

// round 17
// speedup vs baseline: 2.3937x; 1.1610x over previous
#include <cuda_runtime.h>
#include <cuda_bf16.h>
#include <cuda_fp16.h>
#include <cstdint>

#define N_NODES 100000
#define N_EDGES 1600000
#define IN_F    512
#define HID_F   128
#define N_CLS   64
#define HALF_N  50048            // split point, multiple of 128 and 8

// ---------------- device scratch (no allocations allowed) ----------------
__device__ __align__(16) __half g_h1[(size_t)N_NODES * HID_F];   // fp16 h1
__device__ __align__(16) float  g_h2[(size_t)N_NODES * HID_F];
__device__ __align__(16) __half g_h3[(size_t)N_NODES * N_CLS];   // fp16 h3
__device__ int   g_deg[N_NODES + 1];
__device__ int   g_rowptr[N_NODES + 1];
__device__ int   g_fill[N_NODES];
__device__ int2  g_edge[N_EDGES];                 // {col, float_bits(val)}
__device__ __align__(16) __half        g_w1t_f16[HID_F * IN_F];  // [128][512]
__device__ __align__(16) __nv_bfloat16 g_w2t_hi[N_CLS * HID_F];  // [64][128]
__device__ __align__(16) __nv_bfloat16 g_w2t_lo[N_CLS * HID_F];

// ---------------- small helpers ----------------
__device__ __forceinline__ uint32_t smem_u32(const void* p) {
    uint32_t a;
    asm("{ .reg .u64 t; cvta.to.shared.u64 t, %1; cvt.u32.u64 %0, t; }" : "=r"(a) : "l"(p));
    return a;
}
__device__ __forceinline__ void cp16(uint32_t dst, const void* src) {
    asm volatile("cp.async.ca.shared.global [%0], [%1], 16;" :: "r"(dst), "l"(src));
}
#define CP_COMMIT() asm volatile("cp.async.commit_group;" ::: "memory")
#define CP_WAIT(n)  asm volatile("cp.async.wait_group %0;" :: "n"(n) : "memory")

__device__ __forceinline__ void mma_bf16(float* c, const uint32_t* a, const uint32_t* b) {
    asm volatile(
        "mma.sync.aligned.m16n8k16.row.col.f32.bf16.bf16.f32 "
        "{%0,%1,%2,%3}, {%4,%5,%6,%7}, {%8,%9}, {%0,%1,%2,%3};"
        : "+f"(c[0]), "+f"(c[1]), "+f"(c[2]), "+f"(c[3])
        : "r"(a[0]), "r"(a[1]), "r"(a[2]), "r"(a[3]), "r"(b[0]), "r"(b[1]));
}
__device__ __forceinline__ void mma_f16(float* c, const uint32_t* a, const uint32_t* b) {
    asm volatile(
        "mma.sync.aligned.m16n8k16.row.col.f32.f16.f16.f32 "
        "{%0,%1,%2,%3}, {%4,%5,%6,%7}, {%8,%9}, {%0,%1,%2,%3};"
        : "+f"(c[0]), "+f"(c[1]), "+f"(c[2]), "+f"(c[3])
        : "r"(a[0]), "r"(a[1]), "r"(a[2]), "r"(a[3]), "r"(b[0]), "r"(b[1]));
}
__device__ __forceinline__ uint32_t pack_bf16x2(__nv_bfloat16 a, __nv_bfloat16 b) {
    __nv_bfloat162 p; p.x = a; p.y = b;
    return *reinterpret_cast<uint32_t*>(&p);
}
// FAST bf16 split (gemm2 only): hi = truncate, lo = rn(v - hi).
__device__ __forceinline__ uint32_t split2(float2 v, uint32_t& lo) {
    uint32_t u0 = __float_as_uint(v.x);
    uint32_t u1 = __float_as_uint(v.y);
    float l0 = v.x - __uint_as_float(u0 & 0xFFFF0000u);
    float l1 = v.y - __uint_as_float(u1 & 0xFFFF0000u);
    uint32_t hi, lou;
    asm("prmt.b32 %0, %1, %2, 0x7632;" : "=r"(hi) : "r"(u0), "r"(u1));
    asm("cvt.rn.bf16x2.f32 %0, %1, %2;" : "=r"(lou) : "f"(l1), "f"(l0));
    lo = lou;
    return hi;
}
// pack float2 -> fp16x2 (lo = v.x)
__device__ __forceinline__ uint32_t cvt_f16x2(float2 v) {
    uint32_t r;
    asm("cvt.rn.f16x2.f32 %0, %1, %2;" : "=r"(r) : "f"(v.y), "f"(v.x));
    return r;
}

// ---------------- CSR build ----------------
__global__ void zero_deg_kernel() {
    int i = blockIdx.x * blockDim.x + threadIdx.x;
    if (i <= N_NODES) g_deg[i] = 0;
}
__global__ void count_kernel(const int* __restrict__ row) {
    int e = blockIdx.x * blockDim.x + threadIdx.x;
    if (e < N_EDGES) atomicAdd(&g_deg[row[e]], 1);
}
// Coalesced tiled scan (R15-proven).
__global__ __launch_bounds__(1024) void scan_kernel() {
    __shared__ int wsum[32];
    __shared__ int carry_s;
    int t = threadIdx.x, lane = t & 31, wid = t >> 5;
    if (t == 0) carry_s = 0;
    __syncthreads();

    const int NT = (N_NODES + 1023) / 1024;   // 98
    for (int tile = 0; tile < NT; tile++) {
        int i = tile * 1024 + t;
        int d = (i < N_NODES) ? g_deg[i] : 0;
        int v = d;
#pragma unroll
        for (int o = 1; o < 32; o <<= 1) {
            int n = __shfl_up_sync(0xFFFFFFFF, v, o);
            if (lane >= o) v += n;
        }
        if (lane == 31) wsum[wid] = v;
        __syncthreads();
        if (wid == 0) {
            int w = wsum[lane];
#pragma unroll
            for (int o = 1; o < 32; o <<= 1) {
                int n = __shfl_up_sync(0xFFFFFFFF, w, o);
                if (lane >= o) w += n;
            }
            wsum[lane] = w;
        }
        __syncthreads();
        int excl = v - d + (wid ? wsum[wid - 1] : 0);
        int carry = carry_s;
        if (i < N_NODES) {
            g_rowptr[i] = carry + excl;
            g_fill[i]   = carry + excl;
        }
        __syncthreads();
        if (t == 1023) carry_s = carry + excl + d;
        __syncthreads();
    }
    if (t == 0) g_rowptr[N_NODES] = N_EDGES;
}
__global__ void scatter_kernel(const int* __restrict__ row, const int* __restrict__ col,
                               const float* __restrict__ val) {
    int e = blockIdx.x * blockDim.x + threadIdx.x;
    if (e < N_EDGES) {
        int r = row[e];
        int p = atomicAdd(&g_fill[r], 1);
        g_edge[p] = make_int2(col[e], __float_as_int(val[e]));
    }
}

// ---------------- weight prep ----------------
__global__ void prep_w1t_kernel(const float* __restrict__ w1) {
    int idx = blockIdx.x * blockDim.x + threadIdx.x;
    if (idx < IN_F * HID_F) {
        int k = idx >> 7, n = idx & 127;
        g_w1t_f16[n * IN_F + k] = __float2half_rn(w1[idx]);
    }
}
__global__ void prep_w2t_kernel(const float* __restrict__ w2) {
    int idx = blockIdx.x * blockDim.x + threadIdx.x;
    if (idx < HID_F * N_CLS) {
        int k = idx >> 6, n = idx & 63;
        float v = w2[idx];
        __nv_bfloat16 h = __float2bfloat16(v);
        float r = v - __bfloat162float(h);
        g_w2t_hi[n * HID_F + k] = h;
        g_w2t_lo[n * HID_F + k] = __float2bfloat16(r);
    }
}

#define BK  64
#define LDK 72
#define LDA 68

// ---------------- GEMM1: single-product fp16 mma, cp.async pipelined --------
// h1 = x @ w1 + b1 ; A fp32 2-deep ring -> fp16 frags at build; W fp16.
__global__ __launch_bounds__(256) void gemm1_f16_kernel(
    const float* __restrict__ X,
    const __half* __restrict__ Wt,
    const float* __restrict__ Bias,
    __half* __restrict__ O) {
    constexpr int BN = HID_F;            // 128
    constexpr int NITER = IN_F / BK;     // 8
    constexpr int NT = BN / 16;          // 8
    extern __shared__ char smraw[];
    float* Af = (float*)smraw;                                   // [2][128][LDA]
    __half* Bf = (__half*)(Af + 2 * 128 * LDA);                  // [BN][LDK]

    const int t = threadIdx.x;
    const int lane = t & 31;
    const int wid = t >> 5;
    const int warp_m = wid & 3;
    const int warp_n = wid >> 2;
    const int n0 = warp_n * (BN / 2);
    const int row0 = blockIdx.x * 128;
    const int gq = lane >> 2;
    const int gc2 = (lane & 3) * 2;

    const uint32_t af_u = smem_u32(Af);
    const uint32_t bf_u = smem_u32(Bf);

    auto issueA = [&](int s) {
        const int buf = s & 1;
        const int k0 = s * BK;
#pragma unroll
        for (int i = 0; i < 8; i++) {
            int idx = t + i * 256;
            int row = idx >> 4, c4 = (idx & 15) * 4;
            int gr = row0 + row;
            if (gr >= N_NODES) gr = N_NODES - 1;
            cp16(af_u + (uint32_t)(((buf * 128 + row) * LDA + c4) * 4),
                 X + (size_t)gr * IN_F + k0 + c4);
        }
    };
    auto issueB = [&](int s) {
        const int k0 = s * BK;
#pragma unroll
        for (int i = 0; i < 4; i++) {           // BN*8 = 1024 uint4 / 256 thr
            int idx = t + i * 256;
            int row = idx >> 3, q = (idx & 7) * 8;
            cp16(bf_u + (uint32_t)((row * LDK + q) * 2),
                 Wt + (size_t)row * IN_F + k0 + q);
        }
    };

    float acc[2][NT][4];
#pragma unroll
    for (int mt = 0; mt < 2; mt++)
#pragma unroll
        for (int nt = 0; nt < NT; nt++)
#pragma unroll
            for (int i = 0; i < 4; i++) acc[mt][nt][i] = 0.f;

    issueB(0); CP_COMMIT();
    issueA(0); CP_COMMIT();
    issueA(1); CP_COMMIT(); CP_WAIT(1);
    __syncthreads();

    for (int c = 0; c < NITER; c++) {
        const int buf = c & 1;
#pragma unroll
        for (int ks = 0; ks < 4; ks++) {
            const int k = ks * 16;
            uint32_t ah[2][4];
#pragma unroll
            for (int mt = 0; mt < 2; mt++) {
                const int rb = buf * 128 + warp_m * 32 + mt * 16 + gq;
                const float* p0 = &Af[rb * LDA + k + gc2];
                ah[mt][0] = cvt_f16x2(*(const float2*)(p0));
                ah[mt][1] = cvt_f16x2(*(const float2*)(p0 + 8 * LDA));
                ah[mt][2] = cvt_f16x2(*(const float2*)(p0 + 8));
                ah[mt][3] = cvt_f16x2(*(const float2*)(p0 + 8 * LDA + 8));
            }
#pragma unroll
            for (int nt = 0; nt < NT; nt++) {
                const int nrow = n0 + nt * 8 + gq;
                const __half* ph = &Bf[nrow * LDK + k + gc2];
                uint32_t bh[2];
                bh[0] = *(const uint32_t*)(ph);
                bh[1] = *(const uint32_t*)(ph + 8);
#pragma unroll
                for (int mt = 0; mt < 2; mt++)
                    mma_f16(acc[mt][nt], ah[mt], bh);
            }
        }
        __syncthreads();
        if (c + 1 < NITER) {
            issueB(c + 1); CP_COMMIT();
            if (c + 2 < NITER) { issueA(c + 2); CP_COMMIT(); CP_WAIT(1); }
            else               { CP_WAIT(0); }
            __syncthreads();
        }
    }

#pragma unroll
    for (int nt = 0; nt < NT; nt++) {
        const int colb = n0 + nt * 8 + gc2;
        float2 bb = *(const float2*)&Bias[colb];
#pragma unroll
        for (int mt = 0; mt < 2; mt++) {
            int r0 = row0 + warp_m * 32 + mt * 16 + gq;
            if (r0 < N_NODES) {
                __half2 h = __floats2half2_rn(acc[mt][nt][0] + bb.x,
                                              acc[mt][nt][1] + bb.y);
                *(__half2*)(O + (size_t)r0 * BN + colb) = h;
            }
            int r1 = r0 + 8;
            if (r1 < N_NODES) {
                __half2 h = __floats2half2_rn(acc[mt][nt][2] + bb.x,
                                              acc[mt][nt][3] + bb.y);
                *(__half2*)(O + (size_t)r1 * BN + colb) = h;
            }
        }
    }
}

// ---------------- GEMM2: bf16-split 3-product (accurate), half output -------
template <int BN, int K_TOTAL>
__global__ __launch_bounds__(256) void gemm_pipe_kernel(
    const float* __restrict__ X,
    const __nv_bfloat16* __restrict__ Wt_hi,
    const __nv_bfloat16* __restrict__ Wt_lo,
    const float* __restrict__ Bias,
    __half* __restrict__ O,
    int row_base, int row_limit) {
    constexpr int NITER = K_TOTAL / BK;
    extern __shared__ char smraw[];
    float* Af = (float*)smraw;                                   // [2][128][LDA]
    __nv_bfloat16* Bh = (__nv_bfloat16*)(Af + 2 * 128 * LDA);    // [BN][LDK]
    __nv_bfloat16* Bl = Bh + BN * LDK;

    const int t = threadIdx.x;
    const int lane = t & 31;
    const int wid = t >> 5;
    const int warp_m = wid & 3;
    const int warp_n = wid >> 2;
    const int NT = BN / 16;
    const int n0 = warp_n * (BN / 2);
    const int row0 = row_base + blockIdx.x * 128;
    const int gq = lane >> 2;
    const int gc2 = (lane & 3) * 2;

    const uint32_t af_u = smem_u32(Af);
    const uint32_t bh_u = smem_u32(Bh);
    const uint32_t bl_u = smem_u32(Bl);

    auto issueA = [&](int s) {
        const int buf = s & 1;
        const int k0 = s * BK;
#pragma unroll
        for (int i = 0; i < 8; i++) {
            int idx = t + i * 256;
            int row = idx >> 4, c4 = (idx & 15) * 4;
            int gr = row0 + row;
            if (gr >= N_NODES) gr = N_NODES - 1;
            cp16(af_u + (uint32_t)(((buf * 128 + row) * LDA + c4) * 4),
                 X + (size_t)gr * K_TOTAL + k0 + c4);
        }
    };
    auto issueB = [&](int s) {
        const int k0 = s * BK;
        constexpr int BCH = BN * 8 / 256;
#pragma unroll
        for (int i = 0; i < BCH; i++) {
            int idx = t + i * 256;
            int row = idx >> 3, q = (idx & 7) * 8;
            cp16(bh_u + (uint32_t)((row * LDK + q) * 2),
                 Wt_hi + (size_t)row * K_TOTAL + k0 + q);
            cp16(bl_u + (uint32_t)((row * LDK + q) * 2),
                 Wt_lo + (size_t)row * K_TOTAL + k0 + q);
        }
    };

    float acc[2][BN / 16][4];
#pragma unroll
    for (int mt = 0; mt < 2; mt++)
#pragma unroll
        for (int nt = 0; nt < NT; nt++)
#pragma unroll
            for (int i = 0; i < 4; i++) acc[mt][nt][i] = 0.f;

    issueB(0); CP_COMMIT();
    issueA(0); CP_COMMIT();
    if (NITER > 1) { issueA(1); CP_COMMIT(); CP_WAIT(1); }
    else           { CP_WAIT(0); }
    __syncthreads();

    for (int c = 0; c < NITER; c++) {
        const int buf = c & 1;
#pragma unroll
        for (int ks = 0; ks < 4; ks++) {
            const int k = ks * 16;
            uint32_t ah[2][4], al[2][4];
#pragma unroll
            for (int mt = 0; mt < 2; mt++) {
                const int rb = buf * 128 + warp_m * 32 + mt * 16 + gq;
                const float* p0 = &Af[rb * LDA + k + gc2];
                float2 v0 = *(const float2*)(p0);
                float2 v1 = *(const float2*)(p0 + 8 * LDA);
                float2 v2 = *(const float2*)(p0 + 8);
                float2 v3 = *(const float2*)(p0 + 8 * LDA + 8);
                ah[mt][0] = split2(v0, al[mt][0]);
                ah[mt][1] = split2(v1, al[mt][1]);
                ah[mt][2] = split2(v2, al[mt][2]);
                ah[mt][3] = split2(v3, al[mt][3]);
            }
#pragma unroll
            for (int nt = 0; nt < NT; nt++) {
                const int nrow = n0 + nt * 8 + gq;
                const __nv_bfloat16* ph = &Bh[nrow * LDK + k + gc2];
                const __nv_bfloat16* pl = &Bl[nrow * LDK + k + gc2];
                uint32_t bh[2], bl[2];
                bh[0] = *(const uint32_t*)(ph);
                bh[1] = *(const uint32_t*)(ph + 8);
                bl[0] = *(const uint32_t*)(pl);
                bl[1] = *(const uint32_t*)(pl + 8);
#pragma unroll
                for (int mt = 0; mt < 2; mt++) {
                    mma_bf16(acc[mt][nt], ah[mt], bh);
                    mma_bf16(acc[mt][nt], ah[mt], bl);
                    mma_bf16(acc[mt][nt], al[mt], bh);
                }
            }
        }
        __syncthreads();
        if (c + 1 < NITER) {
            issueB(c + 1); CP_COMMIT();
            if (c + 2 < NITER) { issueA(c + 2); CP_COMMIT(); CP_WAIT(1); }
            else               { CP_WAIT(0); }
            __syncthreads();
        }
    }

#pragma unroll
    for (int nt = 0; nt < NT; nt++) {
        const int colb = n0 + nt * 8 + gc2;
        float2 bb = *(const float2*)&Bias[colb];
#pragma unroll
        for (int mt = 0; mt < 2; mt++) {
            int r0 = row0 + warp_m * 32 + mt * 16 + gq;
            if (r0 < row_limit) {
                __half2 h = __floats2half2_rn(acc[mt][nt][0] + bb.x,
                                              acc[mt][nt][1] + bb.y);
                *(__half2*)(O + (size_t)r0 * BN + colb) = h;
            }
            int r1 = r0 + 8;
            if (r1 < row_limit) {
                __half2 h = __floats2half2_rn(acc[mt][nt][2] + bb.x,
                                              acc[mt][nt][3] + bb.y);
                *(__half2*)(O + (size_t)r1 * BN + colb) = h;
            }
        }
    }
}

// ---------------- SpMM1: fp16 h1 gather, fp32 h2 out ------------------------
__global__ __launch_bounds__(256) void spmm1_warp_kernel(
    const __half* __restrict__ h1, float* __restrict__ h2, int node_base) {
    int node = node_base + blockIdx.x * 8 + (threadIdx.x >> 5);
    int lane = threadIdx.x & 31;
    int s = g_rowptr[node], e = g_rowptr[node + 1];

    float4 a0 = make_float4(0.f, 0.f, 0.f, 0.f);
    float4 a1 = a0, a2 = a0, a3 = a0;
    const uint2* H = (const uint2*)h1;     // 4 halves per lane

    auto fma4 = [&](float4& a, float v, uint2 u) {
        float2 f0 = __half22float2(*(__half2*)&u.x);
        float2 f1 = __half22float2(*(__half2*)&u.y);
        a.x += v * f0.x; a.y += v * f0.y;
        a.z += v * f1.x; a.w += v * f1.y;
    };

    int j = s;
    for (; j + 3 < e; j += 4) {
        int2 e0 = g_edge[j],     e1 = g_edge[j + 1];
        int2 e2 = g_edge[j + 2], e3 = g_edge[j + 3];
        uint2 x0 = H[(size_t)e0.x * 32 + lane];
        uint2 x1 = H[(size_t)e1.x * 32 + lane];
        uint2 x2 = H[(size_t)e2.x * 32 + lane];
        uint2 x3 = H[(size_t)e3.x * 32 + lane];
        fma4(a0, __int_as_float(e0.y), x0);
        fma4(a1, __int_as_float(e1.y), x1);
        fma4(a2, __int_as_float(e2.y), x2);
        fma4(a3, __int_as_float(e3.y), x3);
    }
    for (; j < e; j++) {
        int2 ed = g_edge[j];
        uint2 x = H[(size_t)ed.x * 32 + lane];
        fma4(a0, __int_as_float(ed.y), x);
    }
    float4 o;
    o.x = fmaxf(a0.x + a1.x + a2.x + a3.x, 0.f);
    o.y = fmaxf(a0.y + a1.y + a2.y + a3.y, 0.f);
    o.z = fmaxf(a0.z + a1.z + a2.z + a3.z, 0.f);
    o.w = fmaxf(a0.w + a1.w + a2.w + a3.w, 0.f);
    ((float4*)h2)[(size_t)node * 32 + lane] = o;
}

// ---------------- SpMM2: fp16 h3 gather, fp32 out ---------------------------
__global__ __launch_bounds__(256) void spmm2_warp_kernel(
    const __half* __restrict__ h3, float* __restrict__ out) {
    int node = blockIdx.x * 8 + (threadIdx.x >> 5);
    int lane = threadIdx.x & 31;
    int s = g_rowptr[node], e = g_rowptr[node + 1];

    float2 a0 = make_float2(0.f, 0.f);
    float2 a1 = a0, a2 = a0, a3 = a0;
    const uint32_t* H = (const uint32_t*)h3;   // 2 halves per lane

    auto fma2 = [&](float2& a, float v, uint32_t u) {
        float2 f = __half22float2(*(__half2*)&u);
        a.x += v * f.x; a.y += v * f.y;
    };

    int j = s;
    for (; j + 3 < e; j += 4) {
        int2 e0 = g_edge[j],     e1 = g_edge[j + 1];
        int2 e2 = g_edge[j + 2], e3 = g_edge[j + 3];
        uint32_t x0 = H[(size_t)e0.x * 32 + lane];
        uint32_t x1 = H[(size_t)e1.x * 32 + lane];
        uint32_t x2 = H[(size_t)e2.x * 32 + lane];
        uint32_t x3 = H[(size_t)e3.x * 32 + lane];
        fma2(a0, __int_as_float(e0.y), x0);
        fma2(a1, __int_as_float(e1.y), x1);
        fma2(a2, __int_as_float(e2.y), x2);
        fma2(a3, __int_as_float(e3.y), x3);
    }
    for (; j < e; j++) {
        int2 ed = g_edge[j];
        uint32_t x = H[(size_t)ed.x * 32 + lane];
        fma2(a0, __int_as_float(ed.y), x);
    }
    float2 o;
    o.x = a0.x + a1.x + a2.x + a3.x;
    o.y = a0.y + a1.y + a2.y + a3.y;
    ((float2*)out)[(size_t)node * 32 + lane] = o;
}

// ---------------- launch ----------------
#define SMEM_PIPE(BN) (2 * 128 * LDA * 4 + 2 * (BN) * LDK * 2)
#define SMEM_G1F16    (2 * 128 * LDA * 4 + HID_F * LDK * 2)   // 88064

extern "C" void kernel_launch(void* const* d_in, const int* in_sizes, int n_in,
                              void* d_out, int out_size) {
    const float* x       = (const float*)d_in[0];
    const int*   adj_row = (const int*)d_in[1];
    const int*   adj_col = (const int*)d_in[2];
    const float* adj_val = (const float*)d_in[3];
    const float* w1      = (const float*)d_in[4];
    const float* b1      = (const float*)d_in[5];
    const float* w2      = (const float*)d_in[6];
    const float* b2      = (const float*)d_in[7];
    float* out = (float*)d_out;

    __half* h1 = nullptr; float* h2 = nullptr; __half* h3 = nullptr;
    const __half* w1f;
    const __nv_bfloat16 *w2h, *w2l;
    cudaGetSymbolAddress((void**)&h1, g_h1);
    cudaGetSymbolAddress((void**)&h2, g_h2);
    cudaGetSymbolAddress((void**)&h3, g_h3);
    cudaGetSymbolAddress((void**)&w1f, g_w1t_f16);
    cudaGetSymbolAddress((void**)&w2h, g_w2t_hi);
    cudaGetSymbolAddress((void**)&w2l, g_w2t_lo);

    static cudaStream_t s_side = nullptr;
    static cudaEvent_t ev_fork, ev_join, ev_g1, ev_l2;
    static bool init_done = false;
    if (!init_done) {
        cudaFuncSetAttribute(gemm1_f16_kernel,
                             cudaFuncAttributeMaxDynamicSharedMemorySize, SMEM_G1F16);
        cudaFuncSetAttribute(gemm_pipe_kernel<N_CLS, HID_F>,
                             cudaFuncAttributeMaxDynamicSharedMemorySize, SMEM_PIPE(N_CLS));
        cudaStreamCreateWithFlags(&s_side, cudaStreamNonBlocking);
        cudaEventCreateWithFlags(&ev_fork, cudaEventDisableTiming);
        cudaEventCreateWithFlags(&ev_join, cudaEventDisableTiming);
        cudaEventCreateWithFlags(&ev_g1,   cudaEventDisableTiming);
        cudaEventCreateWithFlags(&ev_l2,   cudaEventDisableTiming);
        init_done = true;
    }

    // ---- fork: CSR build on side stream, concurrent with prep + gemm1 ----
    cudaEventRecord(ev_fork, 0);
    cudaStreamWaitEvent(s_side, ev_fork, 0);

    zero_deg_kernel<<<(N_NODES + 256) / 256, 256, 0, s_side>>>();
    count_kernel<<<(N_EDGES + 255) / 256, 256, 0, s_side>>>(adj_row);
    scan_kernel<<<1, 1024, 0, s_side>>>();
    scatter_kernel<<<(N_EDGES + 255) / 256, 256, 0, s_side>>>(adj_row, adj_col, adj_val);
    cudaEventRecord(ev_join, s_side);

    // ---- main stream: weight prep + gemm1 (fp16 single-product) ----
    prep_w1t_kernel<<<(IN_F * HID_F + 255) / 256, 256>>>(w1);
    prep_w2t_kernel<<<(HID_F * N_CLS + 255) / 256, 256>>>(w2);
    gemm1_f16_kernel<<<(N_NODES + 127) / 128, 256, SMEM_G1F16>>>(x, w1f, b1, h1);
    cudaEventRecord(ev_g1, 0);

    // ---- layer-1 aggregation + layer-2 projection, split in halves ----
    cudaStreamWaitEvent(0, ev_join, 0);
    spmm1_warp_kernel<<<HALF_N / 8, 256>>>(h1, h2, 0);
    gemm_pipe_kernel<N_CLS, HID_F>
        <<<HALF_N / 128, 256, SMEM_PIPE(N_CLS)>>>(h2, w2h, w2l, b2, h3, 0, HALF_N);

    cudaStreamWaitEvent(s_side, ev_g1, 0);
    spmm1_warp_kernel<<<(N_NODES - HALF_N) / 8, 256, 0, s_side>>>(h1, h2, HALF_N);
    gemm_pipe_kernel<N_CLS, HID_F>
        <<<(N_NODES - HALF_N + 127) / 128, 256, SMEM_PIPE(N_CLS), s_side>>>(
            h2, w2h, w2l, b2, h3, HALF_N, N_NODES);
    cudaEventRecord(ev_l2, s_side);

    // ---- final aggregation (needs all h3) ----
    cudaStreamWaitEvent(0, ev_l2, 0);
    spmm2_warp_kernel<<<(N_NODES + 7) / 8, 256>>>(h3, out);
}